// round 8
// baseline (speedup 1.0000x reference)
#include <cuda_runtime.h>
#include <cstdint>

// SampleQueryExtractionLayer: bilinear-style 4-tap gather.
// features: [B=4, N=4096(=64x64), C=256] fp32; query_points: [4,8,256,2];
// out: [8192, 256] fp32.
//
// R5 structure (single wave, 2048x128, 2 sequential queries per 64-thread
// group, front-batched gathers) + packed f32x2 epilogue: weights are
// normalized once and packed into (w,w) 64-bit pairs; each float4 blend is
// 2 chains of mul.f32x2 + 3x fma.rn.f32x2 (FFMA2 in SASS), halving the
// post-load FMA instruction tail.

#define EPS_F 0.0001f

typedef unsigned long long u64;

__device__ __forceinline__ u64 pack2(float v) {
    u64 r;
    asm("mov.b64 %0, {%1, %1};" : "=l"(r) : "f"(v));
    return r;
}
__device__ __forceinline__ u64 fma2(u64 a, u64 b, u64 c) {
    u64 d;
    asm("fma.rn.f32x2 %0, %1, %2, %3;" : "=l"(d) : "l"(a), "l"(b), "l"(c));
    return d;
}
__device__ __forceinline__ u64 mul2(u64 a, u64 b) {
    u64 d;
    asm("mul.rn.f32x2 %0, %1, %2;" : "=l"(d) : "l"(a), "l"(b));
    return d;
}

__device__ __forceinline__ void do_query(const float* __restrict__ feat,
                                         float* __restrict__ out,
                                         float2 p, int g, int c4)
{
    const int y0 = __float2int_rd(p.x);
    const int x0 = __float2int_rd(p.y);
    const int b  = g >> 11;                      // 2048 queries per batch

    const ulonglong2* r00 = (const ulonglong2*)feat
                            + (size_t)(b * 4096 + y0 * 64 + x0) * 64 + c4;
    // 4 independent 16B gathers, front-batched.
    const ulonglong2 f00 = __ldg(r00);
    const ulonglong2 f01 = __ldg(r00 + 64);        // (y0, x0+1)
    const ulonglong2 f10 = __ldg(r00 + 64 * 64);   // (y0+1, x0)
    const ulonglong2 f11 = __ldg(r00 + 64 * 65);   // (y0+1, x0+1)

    // Weight math overlaps gather latency (off the address path).
    const float dy = p.x - (float)y0;
    const float dx = p.y - (float)x0;
    const float m00 = fmaxf(0.f, 1.f - (dy + dx)       + EPS_F);
    const float m01 = fmaxf(0.f, 1.f - (dy + 1.f - dx) + EPS_F);
    const float m10 = fmaxf(0.f, 1.f - (1.f - dy + dx) + EPS_F);
    const float m11 = fmaxf(0.f, 1.f - (2.f - dy - dx) + EPS_F);
    const float w00 = m00 * m00;
    const float w01 = m01 * m01;
    const float w10 = m10 * m10;
    const float w11 = m11 * m11;
    const float inv = __fdividef(1.f, w00 + w01 + w10 + w11 + EPS_F);

    // Normalize once, pack into (w,w) f32x2 pairs.
    const u64 p00 = pack2(w00 * inv);
    const u64 p01 = pack2(w01 * inv);
    const u64 p10 = pack2(w10 * inv);
    const u64 p11 = pack2(w11 * inv);

    ulonglong2 acc;
    acc.x = fma2(p00, f00.x, fma2(p01, f01.x, fma2(p10, f10.x, mul2(p11, f11.x))));
    acc.y = fma2(p00, f00.y, fma2(p01, f01.y, fma2(p10, f10.y, mul2(p11, f11.y))));

    // Evict-first store: keep the feature matrix resident in L2.
    __stcs(((ulonglong2*)out) + (size_t)g * 64 + c4, acc);
}

__global__ __launch_bounds__(128)
void sqe_kernel(const float* __restrict__ feat,
                const float* __restrict__ qp,
                float* __restrict__ out)
{
    const int tid = threadIdx.x;
    const int grp = blockIdx.x * 2 + (tid >> 6);   // 0..4095
    const int c4  = tid & 63;

    const int q0 = grp;                            // batches 0-1
    const int q1 = grp + 4096;                     // batches 2-3

    // Both qp loads in flight immediately; one dependent hop total.
    const float2 p0 = __ldg(((const float2*)qp) + q0);
    const float2 p1 = __ldg(((const float2*)qp) + q1);

    do_query(feat, out, p0, q0, c4);
    do_query(feat, out, p1, q1, c4);
}

extern "C" void kernel_launch(void* const* d_in, const int* in_sizes, int n_in,
                              void* d_out, int out_size)
{
    (void)in_sizes; (void)n_in; (void)out_size;
    const float* feat = (const float*)d_in[0];
    const float* qp   = (const float*)d_in[1];
    float* out        = (float*)d_out;

    // 4096 query-groups, 2 per 128-thread block -> 2048 blocks, single wave.
    sqe_kernel<<<2048, 128>>>(feat, qp, out);
}

// round 9
// speedup vs baseline: 1.0257x; 1.0257x over previous
#include <cuda_runtime.h>

// SampleQueryExtractionLayer: bilinear-style 4-tap gather (R5 math, finer CTAs).
// features: [B=4, N=4096(=64x64), C=256] fp32; query_points: [4,8,256,2];
// out: [8192, 256] fp32.
//
// Empirically best structure across 8 rounds: single wave, each 64-thread
// group handles TWO queries (g and g+4096) sequentially so gather data regs
// are reused; both query-point loads issue at t=0 (one dependent hop total);
// weight math (incl. MUFU) stays off the address path; evict-first stores.
// This round: 64-thread CTAs (4096 blocks) for finest scheduler granularity
// -> better single-wave tail balance; per-thread code identical to R5.

#define EPS_F 0.0001f

__device__ __forceinline__ void do_query(const float* __restrict__ feat,
                                         float* __restrict__ out,
                                         float2 p, int g, int c4)
{
    const int y0 = __float2int_rd(p.x);
    const int x0 = __float2int_rd(p.y);
    const int b  = g >> 11;                      // 2048 queries per batch

    const float4* r00 = (const float4*)feat
                        + (size_t)(b * 4096 + y0 * 64 + x0) * 64 + c4;
    // 4 independent gathers, front-batched.
    const float4 f00 = __ldg(r00);
    const float4 f01 = __ldg(r00 + 64);          // (y0, x0+1)
    const float4 f10 = __ldg(r00 + 64 * 64);     // (y0+1, x0)
    const float4 f11 = __ldg(r00 + 64 * 65);     // (y0+1, x0+1)

    // Weight math overlaps the gather latency.
    const float dy = p.x - (float)y0;
    const float dx = p.y - (float)x0;
    const float m00 = fmaxf(0.f, 1.f - (dy + dx)       + EPS_F);
    const float m01 = fmaxf(0.f, 1.f - (dy + 1.f - dx) + EPS_F);
    const float m10 = fmaxf(0.f, 1.f - (1.f - dy + dx) + EPS_F);
    const float m11 = fmaxf(0.f, 1.f - (2.f - dy - dx) + EPS_F);
    const float w00 = m00 * m00;
    const float w01 = m01 * m01;
    const float w10 = m10 * m10;
    const float w11 = m11 * m11;
    const float inv = __fdividef(1.f, w00 + w01 + w10 + w11 + EPS_F);

    float4 acc;
    acc.x = (w00*f00.x + w01*f01.x + w10*f10.x + w11*f11.x) * inv;
    acc.y = (w00*f00.y + w01*f01.y + w10*f10.y + w11*f11.y) * inv;
    acc.z = (w00*f00.z + w01*f01.z + w10*f10.z + w11*f11.z) * inv;
    acc.w = (w00*f00.w + w01*f01.w + w10*f10.w + w11*f11.w) * inv;

    // Evict-first store: keep the feature matrix resident in L2.
    __stcs(((float4*)out) + (size_t)g * 64 + c4, acc);
}

__global__ __launch_bounds__(64)
void sqe_kernel(const float* __restrict__ feat,
                const float* __restrict__ qp,
                float* __restrict__ out)
{
    const int c4  = threadIdx.x;                 // 0..63, float4 lane in C
    const int grp = blockIdx.x;                  // 0..4095

    const int q0 = grp;                          // batches 0-1
    const int q1 = grp + 4096;                   // batches 2-3

    // Both qp loads in flight immediately (broadcast within the block).
    const float2 p0 = __ldg(((const float2*)qp) + q0);
    const float2 p1 = __ldg(((const float2*)qp) + q1);

    do_query(feat, out, p0, q0, c4);
    do_query(feat, out, p1, q1, c4);
}

extern "C" void kernel_launch(void* const* d_in, const int* in_sizes, int n_in,
                              void* d_out, int out_size)
{
    (void)in_sizes; (void)n_in; (void)out_size;
    const float* feat = (const float*)d_in[0];
    const float* qp   = (const float*)d_in[1];
    float* out        = (float*)d_out;

    // 4096 groups x 2 sequential queries = 8192 queries, single wave.
    sqe_kernel<<<4096, 64>>>(feat, qp, out);
}